// round 15
// baseline (speedup 1.0000x reference)
#include <cuda_runtime.h>
#include <cuda_fp16.h>

#define ROWS  128            // rows per CTA (cluster of 2 covers 256)
#define P2    129            // row pitch in half2 words; 129 % 32 == 1 -> bank = (i + j) % 32
#define NTH   512
#define ITERS 5

#define SMEM_E      (ROWS * P2 * 4)          // 66048 B
#define OFF_EXCH    SMEM_E                   // float[2][2][256] double-buffered = 4096 B
#define OFF_U       (OFF_EXCH + 4096)        // float[128]
#define OFF_W       (OFF_U + 512)            // float[256]
#define OFF_U2      (OFF_W + 1024)           // ull[128]: (u_i, u_i) duplicated pairs
#define SMEM_TOTAL  (OFF_U2 + 1024)          // 72704 B -> 3 CTAs/SM (218112 <= 227KB)

typedef unsigned long long ull;

__device__ __forceinline__ ull pack2(float x, float y) {
    ull r; asm("mov.b64 %0, {%1, %2};" : "=l"(r) : "f"(x), "f"(y)); return r;
}
__device__ __forceinline__ void fma2(ull& d, ull a, ull b) {
    asm("fma.rn.f32x2 %0, %1, %2, %3;" : "=l"(d) : "l"(a), "l"(b), "l"(d));
}
__device__ __forceinline__ float2 unpack2(ull v) {
    float2 f; asm("mov.b64 {%0, %1}, %2;" : "=f"(f.x), "=f"(f.y) : "l"(v)); return f;
}

__global__ __launch_bounds__(NTH, 3) __cluster_dims__(2, 1, 1)
void sinkhorn_kernel(const float* __restrict__ logits,
                     const int* __restrict__ free_agents_num,
                     const int* __restrict__ tasks_num,
                     float* __restrict__ out)
{
    extern __shared__ __align__(16) unsigned char sm[];
    half2* E2   = reinterpret_cast<half2*>(sm);
    float* exch = reinterpret_cast<float*>(sm + OFF_EXCH);  // [buf][rank][256]
    float* u    = reinterpret_cast<float*>(sm + OFF_U);
    float* w    = reinterpret_cast<float*>(sm + OFF_W);
    ull*   u2   = reinterpret_cast<ull*>(sm + OFF_U2);

    const int rank = blockIdx.x & 1;
    const int b    = blockIdx.x >> 1;
    const int t    = threadIdx.x;
    const int na   = free_agents_num[b];
    const int nt   = tasks_num[b];
    const int row0 = rank * ROWS;

    const float4* __restrict__ L4 =
        reinterpret_cast<const float4*>(logits) + (size_t)b * 16384 + (size_t)rank * 8192;
    float4* __restrict__ O4 =
        reinterpret_cast<float4*>(out) + (size_t)b * 16384 + (size_t)rank * 8192;
    float2* __restrict__ O2 = reinterpret_cast<float2*>(O4);

    // Degenerate batch: both cluster CTAs share b -> both take this branch (barrier-safe).
    if (na == 0 || nt == 0) {
        float4 z = make_float4(0.f, 0.f, 0.f, 0.f);
        #pragma unroll
        for (int k = 0; k < 8192 / NTH; ++k)
            O4[t + k * NTH] = z;
        return;
    }

    // ---- Phase 1: HBM -> E(fp16) + FUSED iteration-0 row sums (w == 1) ----
    // scr uses exchange BUFFER 1: the peer's earliest DSMEM stores target buffer 0 and
    // cannot land before the it=0 cluster barrier (which we must also reach) -> no race.
    float* scr = exch + 512;
    #pragma unroll 4
    for (int k = 0; k < 8192 / NTH; ++k) {
        int idx = t + k * NTH;
        int i = idx >> 6;                  // 64 float4 per row; all 32 lanes share one row
        int j = (idx & 63) << 2;
        half2 h01 = __floats2half2_rn(0.f, 0.f);
        half2 h23 = h01;
        float se = 0.f;
        if ((row0 + i) < na && j < nt) {
            float4 v = L4[idx];
            float e0 = __expf(v.x);
            float e1 = (j + 1) < nt ? __expf(v.y) : 0.f;
            float e2 = (j + 2) < nt ? __expf(v.z) : 0.f;
            float e3 = (j + 3) < nt ? __expf(v.w) : 0.f;
            h01 = __floats2half2_rn(e0, e1);
            h23 = __floats2half2_rn(e2, e3);
            se = (e0 + e1) + (e2 + e3);
        }
        half2* row = E2 + i * P2 + (j >> 1);
        row[0] = h01;
        row[1] = h23;
        se += __shfl_xor_sync(0xffffffffu, se, 16);
        se += __shfl_xor_sync(0xffffffffu, se, 8);
        se += __shfl_xor_sync(0xffffffffu, se, 4);
        se += __shfl_xor_sync(0xffffffffu, se, 2);
        se += __shfl_xor_sync(0xffffffffu, se, 1);
        if ((t & 31) == 0) scr[2 * i + ((t >> 5) & 1)] = se;
    }
    __syncthreads();
    if (t < 128) {
        float S = scr[2 * t] + scr[2 * t + 1];
        float ui = ((row0 + t) < na) ? 1.0f / S : 0.f;
        u[t]  = ui;
        u2[t] = pack2(ui, ui);
    }
    __syncthreads();

    // 4-way split, block-granular trimming (proven structure).
    const int rrow = t >> 2, q = t & 3;
    const bool rvalid = (row0 + rrow) < na;
    const int ntp = (nt + 1) >> 1;
    const int nrl = min(max(na - row0, 0), ROWS);
    int Mr = (ntp > 8 * q) ? (((ntp - 8 * q - 1) >> 5) + 1) : 0;   // <= 4
    int Mc = (nrl > 8 * q) ? (((nrl - 8 * q - 1) >> 5) + 1) : 0;   // <= 4
    if (!rvalid) Mr = 0;
    if (2 * rrow >= nt) Mc = 0;

    unsigned raddr0;
    {
        unsigned laddr = (unsigned)__cvta_generic_to_shared(&exch[rank * 256 + 2 * rrow]);
        asm("mapa.shared::cluster.u32 %0, %1, %2;" : "=r"(raddr0) : "r"(laddr), "r"(rank ^ 1));
    }

    const half2* Er  = E2 + rrow * P2 + 8 * q;
    const ull*   Wr8 = reinterpret_cast<const ull*>(w) + 8 * q;    // (w[2j], w[2j+1]) pairs
    const half2* Ec  = E2 + (8 * q) * P2 + rrow;
    const ull*   Uc8 = u2 + 8 * q;                                 // (u_i, u_i) pairs

    // 5 x (col-norm then row-norm), row-norm skipped on the last trip:
    // with the fused row-norm above = exactly 5 row + 5 col norms.
    for (int it = 0; it < ITERS; ++it) {
        const int bufo = (it & 1) * 512;

        // ---- Col pass: T_jp partial = sum_i E_i,jp * u_i  (packed f32x2 FMA) ----
        ull ce = 0ULL, co = 0ULL;   // (x,y) accumulators, even/odd c
        {
            const half2* p  = Ec;
            const ull*   up = Uc8;
            for (int m = 0; m < Mc; ++m) {
                #pragma unroll
                for (int c = 0; c < 8; ++c) {
                    float2 e = __half22float2(p[c * P2]);   // conflict-free (bank = i + jp)
                    ull ep = pack2(e.x, e.y);
                    if (c & 1) fma2(co, ep, up[c]);         // LDS.64 broadcast of (u,u)
                    else       fma2(ce, ep, up[c]);
                }
                p += 32 * P2; up += 32;
            }
        }
        float2 fe = unpack2(ce), fo = unpack2(co);
        float ax = fe.x + fo.x, ay = fe.y + fo.y;
        ax += __shfl_xor_sync(0xffffffffu, ax, 1);
        ay += __shfl_xor_sync(0xffffffffu, ay, 1);
        ax += __shfl_xor_sync(0xffffffffu, ax, 2);
        ay += __shfl_xor_sync(0xffffffffu, ay, 2);
        if (q == 0) {
            exch[bufo + rank * 256 + 2 * rrow]     = ax;
            exch[bufo + rank * 256 + 2 * rrow + 1] = ay;
            unsigned ra = raddr0 + (unsigned)(bufo * 4);
            asm volatile("st.shared::cluster.f32 [%0],   %1;" :: "r"(ra), "f"(ax) : "memory");
            asm volatile("st.shared::cluster.f32 [%0+4], %1;" :: "r"(ra), "f"(ay) : "memory");
        }
        asm volatile("barrier.cluster.arrive.aligned;" ::: "memory");
        asm volatile("barrier.cluster.wait.aligned;"   ::: "memory");

        if (t < 128) {
            int j0 = 2 * t, j1 = j0 + 1;
            float T0 = exch[bufo + j0] + exch[bufo + 256 + j0];
            float T1 = exch[bufo + j1] + exch[bufo + 256 + j1];
            w[j0] = (j0 < nt) ? 1.0f / T0 : 0.f;
            w[j1] = (j1 < nt) ? 1.0f / T1 : 0.f;
        }
        __syncthreads();

        if (it < ITERS - 1) {
            // ---- Row pass: S_i = sum_j E_ij * w_j  (packed f32x2 FMA) ----
            ull re = 0ULL, ro = 0ULL;
            {
                const half2* p  = Er;
                const ull*   wp = Wr8;
                for (int m = 0; m < Mr; ++m) {
                    #pragma unroll
                    for (int c = 0; c < 8; ++c) {
                        float2 e = __half22float2(p[c]);    // conflict-free
                        ull ep = pack2(e.x, e.y);
                        if (c & 1) fma2(ro, ep, wp[c]);     // natural (w,w') pair load
                        else       fma2(re, ep, wp[c]);
                    }
                    p += 32; wp += 32;
                }
            }
            float2 ge = unpack2(re), go = unpack2(ro);
            float S = (ge.x + go.x) + (ge.y + go.y);
            S += __shfl_xor_sync(0xffffffffu, S, 1);
            S += __shfl_xor_sync(0xffffffffu, S, 2);
            if (q == 0) {
                float ui = rvalid ? 1.0f / S : 0.f;
                u[rrow]  = ui;
                u2[rrow] = pack2(ui, ui);
            }
            __syncthreads();
        }
    }

    // ---- Phase 3: out = E * u_i * w_j * exp(1e-6), exactly this CTA's 8192 float4 ----
    {
        const float C = 1.0000010000005f;
        const int l = t & 31;
        float2 wr[4];
        #pragma unroll
        for (int s = 0; s < 4; ++s)
            wr[s] = *reinterpret_cast<const float2*>(w + 2 * (l + 32 * s));
        #pragma unroll 2
        for (int k = 0; k < 8; ++k) {
            int idx = t + k * NTH;         // < 4096
            int row = idx >> 5;            // < 128, warp-uniform
            if ((row0 + row) < na) {
                float ui = u[row] * C;
                #pragma unroll
                for (int s = 0; s < 4; ++s) {
                    float2 e = __half22float2(E2[row * P2 + l + 32 * s]);
                    O2[row * 128 + l + 32 * s] = make_float2(e.x * ui * wr[s].x,
                                                             e.y * ui * wr[s].y);
                }
            } else {
                float2 z2 = make_float2(0.f, 0.f);
                #pragma unroll
                for (int s = 0; s < 4; ++s)
                    O2[row * 128 + l + 32 * s] = z2;
            }
        }
    }
}

extern "C" void kernel_launch(void* const* d_in, const int* in_sizes, int n_in,
                              void* d_out, int out_size)
{
    const float* logits = (const float*)d_in[0];
    const int*   agents = (const int*)d_in[1];
    const int*   tasks  = (const int*)d_in[2];
    float*       out    = (float*)d_out;
    const int B = in_sizes[1];

    cudaFuncSetAttribute(sinkhorn_kernel,
                         cudaFuncAttributeMaxDynamicSharedMemorySize, SMEM_TOTAL);

    sinkhorn_kernel<<<2 * B, NTH, SMEM_TOTAL>>>(logits, agents, tasks, out);
}

// round 16
// speedup vs baseline: 1.1083x; 1.1083x over previous
#include <cuda_runtime.h>
#include <cuda_fp16.h>

#define ROWS  128            // rows per CTA (cluster of 2 covers 256)
#define P2    129            // row pitch in half2 words; 129 % 32 == 1 -> bank = (i + j) % 32
#define NTH   512
#define ITERS 5

#define SMEM_E      (ROWS * P2 * 4)          // 66048 B
#define OFF_EXCH    SMEM_E                   // float[2][2][256] double-buffered = 4096 B
#define OFF_U       (OFF_EXCH + 4096)        // float[128]
#define OFF_W       (OFF_U + 512)            // float[256]
#define OFF_BAR     (OFF_W + 1024)           // mbarrier (8 B, padded to 16)
#define SMEM_TOTAL  (OFF_BAR + 16)           // 71696 B -> 3 CTAs/SM

__global__ __launch_bounds__(NTH, 3) __cluster_dims__(2, 1, 1)
void sinkhorn_kernel(const float* __restrict__ logits,
                     const int* __restrict__ free_agents_num,
                     const int* __restrict__ tasks_num,
                     float* __restrict__ out)
{
    extern __shared__ __align__(16) unsigned char sm[];
    half2* E2   = reinterpret_cast<half2*>(sm);
    float* exch = reinterpret_cast<float*>(sm + OFF_EXCH);  // [buf][rank][256]
    float* u    = reinterpret_cast<float*>(sm + OFF_U);
    float* w    = reinterpret_cast<float*>(sm + OFF_W);

    const int rank = blockIdx.x & 1;
    const int b    = blockIdx.x >> 1;
    const int t    = threadIdx.x;
    const int na   = free_agents_num[b];
    const int nt   = tasks_num[b];
    const int row0 = rank * ROWS;

    const float4* __restrict__ L4 =
        reinterpret_cast<const float4*>(logits) + (size_t)b * 16384 + (size_t)rank * 8192;
    float4* __restrict__ O4 =
        reinterpret_cast<float4*>(out) + (size_t)b * 16384 + (size_t)rank * 8192;
    float2* __restrict__ O2 = reinterpret_cast<float2*>(O4);

    // Degenerate batch: both cluster CTAs share b -> both take this branch together,
    // so neither issues cluster sync / mbarrier traffic. Barrier-safe.
    if (na == 0 || nt == 0) {
        float4 z = make_float4(0.f, 0.f, 0.f, 0.f);
        #pragma unroll
        for (int k = 0; k < 8192 / NTH; ++k)
            O4[t + k * NTH] = z;
        return;
    }

    const unsigned bar = (unsigned)__cvta_generic_to_shared(sm + OFF_BAR);
    unsigned peer_bar;
    asm("mapa.shared::cluster.u32 %0, %1, %2;" : "=r"(peer_bar) : "r"(bar), "r"(rank ^ 1));

    // Init my mbarrier: expects 128 arrivals per phase, all from the PEER's q==0 threads.
    if (t == 0) {
        asm volatile("mbarrier.init.shared.b64 [%0], 128;" :: "r"(bar) : "memory");
    }
    // Cluster rendezvous (once): peer must not arrive on my barrier before init lands.
    asm volatile("barrier.cluster.arrive.aligned;" ::: "memory");
    asm volatile("barrier.cluster.wait.aligned;"   ::: "memory");

    // ---- Phase 1: HBM -> E(fp16) + FUSED iteration-0 row sums (w == 1) ----
    // scr uses exchange BUFFER 1: the peer's earliest DSMEM stores target buffer 0, and
    // it cannot issue buffer-1 (it=1) stores until its it=0 wait completes, which needs
    // MY it=0 arrivals -- sent only after my phase 1 finishes. No race with scr.
    float* scr = exch + 512;
    #pragma unroll 4
    for (int k = 0; k < 8192 / NTH; ++k) {
        int idx = t + k * NTH;
        int i = idx >> 6;                  // 64 float4 per row; all 32 lanes share one row
        int j = (idx & 63) << 2;
        half2 h01 = __floats2half2_rn(0.f, 0.f);
        half2 h23 = h01;
        float se = 0.f;
        if ((row0 + i) < na && j < nt) {
            float4 v = L4[idx];
            float e0 = __expf(v.x);
            float e1 = (j + 1) < nt ? __expf(v.y) : 0.f;
            float e2 = (j + 2) < nt ? __expf(v.z) : 0.f;
            float e3 = (j + 3) < nt ? __expf(v.w) : 0.f;
            h01 = __floats2half2_rn(e0, e1);
            h23 = __floats2half2_rn(e2, e3);
            se = (e0 + e1) + (e2 + e3);
        }
        half2* row = E2 + i * P2 + (j >> 1);
        row[0] = h01;
        row[1] = h23;
        se += __shfl_xor_sync(0xffffffffu, se, 16);
        se += __shfl_xor_sync(0xffffffffu, se, 8);
        se += __shfl_xor_sync(0xffffffffu, se, 4);
        se += __shfl_xor_sync(0xffffffffu, se, 2);
        se += __shfl_xor_sync(0xffffffffu, se, 1);
        if ((t & 31) == 0) scr[2 * i + ((t >> 5) & 1)] = se;
    }
    __syncthreads();
    if (t < 128) {
        float S = scr[2 * t] + scr[2 * t + 1];
        u[t] = ((row0 + t) < na) ? 1.0f / S : 0.f;
    }
    __syncthreads();

    // 4-way split, block-granular trimming (proven R13/R14 structure).
    const int rrow = t >> 2, q = t & 3;
    const bool rvalid = (row0 + rrow) < na;
    const int ntp = (nt + 1) >> 1;
    const int nrl = min(max(na - row0, 0), ROWS);
    int Mr = (ntp > 8 * q) ? (((ntp - 8 * q - 1) >> 5) + 1) : 0;   // <= 4
    int Mc = (nrl > 8 * q) ? (((nrl - 8 * q - 1) >> 5) + 1) : 0;   // <= 4
    if (!rvalid) Mr = 0;
    if (2 * rrow >= nt) Mc = 0;

    unsigned raddr0;
    {
        unsigned laddr = (unsigned)__cvta_generic_to_shared(&exch[rank * 256 + 2 * rrow]);
        asm("mapa.shared::cluster.u32 %0, %1, %2;" : "=r"(raddr0) : "r"(laddr), "r"(rank ^ 1));
    }

    const half2*  Er = E2 + rrow * P2 + 8 * q;
    const float2* Wr = reinterpret_cast<const float2*>(w) + 8 * q;
    const half2*  Ec = E2 + (8 * q) * P2 + rrow;
    const float*  Uc = u + 8 * q;

    // 5 x (col-norm then row-norm), row-norm skipped on the last trip:
    // with the fused row-norm above = exactly 5 row + 5 col norms.
    for (int it = 0; it < ITERS; ++it) {
        const int bufo = (it & 1) * 512;

        // ---- Col pass: T_jp partial = sum_i E_i,jp * u_i ----
        float x0 = 0.f, y0 = 0.f, x1 = 0.f, y1 = 0.f;
        {
            const half2* p  = Ec;
            const float* up = Uc;
            for (int m = 0; m < Mc; ++m) {
                #pragma unroll
                for (int c = 0; c < 8; ++c) {
                    float2 e = __half22float2(p[c * P2]);
                    float uu = up[c];
                    if (c & 1) { x1 = fmaf(e.x, uu, x1); y1 = fmaf(e.y, uu, y1); }
                    else       { x0 = fmaf(e.x, uu, x0); y0 = fmaf(e.y, uu, y0); }
                }
                p += 32 * P2; up += 32;
            }
        }
        float ax = x0 + x1, ay = y0 + y1;
        ax += __shfl_xor_sync(0xffffffffu, ax, 1);
        ay += __shfl_xor_sync(0xffffffffu, ay, 1);
        ax += __shfl_xor_sync(0xffffffffu, ax, 2);
        ay += __shfl_xor_sync(0xffffffffu, ay, 2);
        if (q == 0) {
            // Local half: plain stores (ordered for local readers by __syncthreads below).
            exch[bufo + rank * 256 + 2 * rrow]     = ax;
            exch[bufo + rank * 256 + 2 * rrow + 1] = ay;
            // Peer half: DSMEM stores, then release-arrive on the PEER's barrier.
            unsigned ra = raddr0 + (unsigned)(bufo * 4);
            asm volatile("st.shared::cluster.f32 [%0],   %1;" :: "r"(ra), "f"(ax) : "memory");
            asm volatile("st.shared::cluster.f32 [%0+4], %1;" :: "r"(ra), "f"(ay) : "memory");
            asm volatile("mbarrier.arrive.release.cluster.shared::cluster.b64 _, [%0];"
                         :: "r"(peer_bar) : "memory");
        }
        __syncthreads();

        if (t < 128) {
            // Wait for the peer's 128 arrivals of this phase (acquire pairs with their release).
            asm volatile(
                "{\n\t.reg .pred p;\n\t"
                "WAIT_%=:\n\t"
                "mbarrier.try_wait.parity.acquire.cluster.shared::cta.b64 p, [%0], %1, 0x989680;\n\t"
                "@!p bra WAIT_%=;\n\t}"
                :: "r"(bar), "r"(it & 1) : "memory");
            int j0 = 2 * t, j1 = j0 + 1;
            float T0 = exch[bufo + j0] + exch[bufo + 256 + j0];
            float T1 = exch[bufo + j1] + exch[bufo + 256 + j1];
            w[j0] = (j0 < nt) ? 1.0f / T0 : 0.f;
            w[j1] = (j1 < nt) ? 1.0f / T1 : 0.f;
        }
        __syncthreads();

        if (it < ITERS - 1) {
            // ---- Row pass: S_i = sum_j E_ij * w_j ----
            float a0 = 0.f, a1 = 0.f, a2 = 0.f, a3 = 0.f;
            {
                const half2*  p  = Er;
                const float2* wp = Wr;
                for (int m = 0; m < Mr; ++m) {
                    #pragma unroll
                    for (int c = 0; c < 8; ++c) {
                        float2 e  = __half22float2(p[c]);
                        float2 ww = wp[c];
                        if (c & 1) { a2 = fmaf(e.x, ww.x, a2); a3 = fmaf(e.y, ww.y, a3); }
                        else       { a0 = fmaf(e.x, ww.x, a0); a1 = fmaf(e.y, ww.y, a1); }
                    }
                    p += 32; wp += 32;
                }
            }
            float S = (a0 + a2) + (a1 + a3);
            S += __shfl_xor_sync(0xffffffffu, S, 1);
            S += __shfl_xor_sync(0xffffffffu, S, 2);
            if (q == 0) u[rrow] = rvalid ? 1.0f / S : 0.f;
            __syncthreads();
        }
    }

    // ---- Phase 3: out = E * u_i * w_j * exp(1e-6), exactly this CTA's 8192 float4 ----
    {
        const float C = 1.0000010000005f;
        const int l = t & 31;
        float2 wr[4];
        #pragma unroll
        for (int s = 0; s < 4; ++s)
            wr[s] = *reinterpret_cast<const float2*>(w + 2 * (l + 32 * s));
        #pragma unroll 2
        for (int k = 0; k < 8; ++k) {
            int idx = t + k * NTH;         // < 4096
            int row = idx >> 5;            // < 128, warp-uniform
            if ((row0 + row) < na) {
                float ui = u[row] * C;
                #pragma unroll
                for (int s = 0; s < 4; ++s) {
                    float2 e = __half22float2(E2[row * P2 + l + 32 * s]);
                    O2[row * 128 + l + 32 * s] = make_float2(e.x * ui * wr[s].x,
                                                             e.y * ui * wr[s].y);
                }
            } else {
                float2 z2 = make_float2(0.f, 0.f);
                #pragma unroll
                for (int s = 0; s < 4; ++s)
                    O2[row * 128 + l + 32 * s] = z2;
            }
        }
    }
}

extern "C" void kernel_launch(void* const* d_in, const int* in_sizes, int n_in,
                              void* d_out, int out_size)
{
    const float* logits = (const float*)d_in[0];
    const int*   agents = (const int*)d_in[1];
    const int*   tasks  = (const int*)d_in[2];
    float*       out    = (float*)d_out;
    const int B = in_sizes[1];

    cudaFuncSetAttribute(sinkhorn_kernel,
                         cudaFuncAttributeMaxDynamicSharedMemorySize, SMEM_TOTAL);

    sinkhorn_kernel<<<2 * B, NTH, SMEM_TOTAL>>>(logits, agents, tasks, out);
}